// round 1
// baseline (speedup 1.0000x reference)
#include <cuda_runtime.h>
#include <cstdint>

#define Z 4
#define N 256
#define CIN 32
#define COUT 32
#define HID 64
#define ZN (Z * N)
#define GSZ (HID * COUT)   // 2048 per point

// Scratch: per-point precomputes (no cudaMalloc allowed)
__device__ float g_U[ZN * HID];      // U = geo @ W1 (NO b1)
__device__ float g_G[(size_t)ZN * GSZ]; // G[p][h][i] = sum_j W2[h, i*32+j] * f[p][j]
__device__ float g_Bf[ZN * COUT];    // Bf[p][i]   = sum_j b2[i*32+j] * f[p][j]

// ---------------------------------------------------------------------------
// Pass 1a: U and Bf (tiny). One block per point, 128 threads.
// ---------------------------------------------------------------------------
__global__ void __launch_bounds__(128) pre_small(
    const float* __restrict__ geo, const float* __restrict__ feat,
    const float* __restrict__ W1, const float* __restrict__ b2) {
    int p = blockIdx.x;
    int t = threadIdx.x;
    __shared__ float fs[CIN];
    __shared__ float g3[3];
    if (t < CIN) fs[t] = feat[p * CIN + t];
    if (t >= 32 && t < 35) g3[t - 32] = geo[p * 3 + (t - 32)];
    __syncthreads();
    if (t < HID) {
        float u = g3[0] * W1[t] + g3[1] * W1[HID + t] + g3[2] * W1[2 * HID + t];
        g_U[p * HID + t] = u;
    } else if (t < HID + COUT) {
        int i = t - HID;
        float s = 0.f;
        #pragma unroll
        for (int j = 0; j < CIN; ++j) s += b2[i * CIN + j] * fs[j];
        g_Bf[p * COUT + i] = s;
    }
}

// ---------------------------------------------------------------------------
// Pass 1b: G precompute, tiled 16 points/block so W2 (256 KB) streams only
// 64x total (16 MB of L2 traffic instead of 256 MB).
// Each thread owns 8 (h,i) entries; W2 row chunk held in regs, reused x16.
// ---------------------------------------------------------------------------
#define PTS 16
__global__ void __launch_bounds__(256) pre_G(
    const float* __restrict__ feat, const float* __restrict__ W2) {
    int pbase = blockIdx.x * PTS;
    int t = threadIdx.x;
    __shared__ float4 fs4[PTS][CIN / 4];   // [16][8]
    for (int idx = t; idx < PTS * (CIN / 4); idx += 256) {
        int p = idx >> 3, j4 = idx & 7;
        fs4[p][j4] = ((const float4*)feat)[(size_t)(pbase + p) * (CIN / 4) + j4];
    }
    __syncthreads();
    for (int e = t; e < GSZ; e += 256) {
        int h = e >> 5, i = e & 31;
        const float4* wrow = (const float4*)(W2 + (size_t)h * (COUT * CIN) + i * CIN);
        float4 w[8];
        #pragma unroll
        for (int j4 = 0; j4 < 8; ++j4) w[j4] = wrow[j4];
        float acc[PTS];
        #pragma unroll
        for (int p = 0; p < PTS; ++p) acc[p] = 0.f;
        #pragma unroll
        for (int j4 = 0; j4 < 8; ++j4) {
            #pragma unroll
            for (int p = 0; p < PTS; ++p) {
                float4 fv = fs4[p][j4];
                acc[p] += w[j4].x * fv.x + w[j4].y * fv.y
                        + w[j4].z * fv.z + w[j4].w * fv.w;
            }
        }
        #pragma unroll
        for (int p = 0; p < PTS; ++p)
            g_G[(size_t)(pbase + p) * GSZ + e] = acc[p];
    }
}

// ---------------------------------------------------------------------------
// Pass 2: the pair kernel. One block per (z,b) point; thread a handles row a.
//   h[h'] = relu(Ub[h'] + b1[h'] - Ua[h'])
//   acc[i] = Bf[i] + sum_h h[h'] * G[h'][i]
// G tile lives in smem; every thread reads the SAME address each step
// (pure broadcast, no bank conflicts). Inner product uses packed
// fma.rn.f32x2 (FFMA2) for 2x fp32 throughput.
// ---------------------------------------------------------------------------
__global__ void __launch_bounds__(256) pair_kernel(
    const float* __restrict__ b1, float* __restrict__ out) {
    int p = blockIdx.x;          // z*N + b
    int z = p >> 8;
    int b = p & 255;
    int a = threadIdx.x;

    __shared__ float Gs[GSZ];    // 8 KB
    __shared__ float Ubs[HID];
    __shared__ float Bfs[COUT];

    {
        const float4* gsrc = (const float4*)(g_G + (size_t)p * GSZ);
        float4* gdst = (float4*)Gs;
        #pragma unroll
        for (int k = 0; k < 2; ++k) gdst[a + 256 * k] = gsrc[a + 256 * k];
        if (a < HID) Ubs[a] = g_U[p * HID + a] + b1[a];
        else if (a < HID + COUT) Bfs[a - HID] = g_Bf[p * COUT + (a - HID)];
    }
    __syncthreads();

    // accumulators: 32 fp32 as 16 packed f32x2 (in 8 ulonglong2)
    ulonglong2 acc[8];
    {
        const ulonglong2* bf = (const ulonglong2*)Bfs;
        #pragma unroll
        for (int q = 0; q < 8; ++q) acc[q] = bf[q];
    }

    const float* Ua = g_U + (size_t)(z * N + a) * HID;

    #pragma unroll
    for (int half = 0; half < 2; ++half) {
        // hidden activations for this half (32 regs live at a time)
        float hreg[32];
        const float4* u4 = (const float4*)(Ua + half * 32);
        #pragma unroll
        for (int h4 = 0; h4 < 8; ++h4) {
            float4 u = u4[h4];
            int hb = half * 32 + h4 * 4;
            hreg[h4 * 4 + 0] = fmaxf(Ubs[hb + 0] - u.x, 0.f);
            hreg[h4 * 4 + 1] = fmaxf(Ubs[hb + 1] - u.y, 0.f);
            hreg[h4 * 4 + 2] = fmaxf(Ubs[hb + 2] - u.z, 0.f);
            hreg[h4 * 4 + 3] = fmaxf(Ubs[hb + 3] - u.w, 0.f);
        }
        #pragma unroll
        for (int hh = 0; hh < 32; ++hh) {
            int h = half * 32 + hh;
            unsigned long long vv;
            unsigned int hb = __float_as_uint(hreg[hh]);
            asm("mov.b64 %0, {%1, %1};" : "=l"(vv) : "r"(hb));
            const ulonglong2* grow = (const ulonglong2*)(Gs + h * COUT);
            #pragma unroll
            for (int q = 0; q < 8; ++q) {
                ulonglong2 g = grow[q];   // LDS.128 broadcast
                asm("fma.rn.f32x2 %0, %1, %2, %0;"
                    : "+l"(acc[q].x) : "l"(vv), "l"(g.x));
                asm("fma.rn.f32x2 %0, %1, %2, %0;"
                    : "+l"(acc[q].y) : "l"(vv), "l"(g.y));
            }
        }
    }

    // out[z, a, b, i] : 128 contiguous bytes per thread -> 8x STG.128
    size_t obase = (((size_t)(z * N + a)) * N + b) * COUT;
    ulonglong2* o2 = (ulonglong2*)(out + obase);
    #pragma unroll
    for (int q = 0; q < 8; ++q) o2[q] = acc[q];
}

// ---------------------------------------------------------------------------
extern "C" void kernel_launch(void* const* d_in, const int* in_sizes, int n_in,
                              void* d_out, int out_size) {
    const float* feat = (const float*)d_in[0];
    const float* geo  = (const float*)d_in[1];
    const float* W1   = (const float*)d_in[2];
    const float* b1   = (const float*)d_in[3];
    const float* W2   = (const float*)d_in[4];
    const float* b2   = (const float*)d_in[5];
    float* out = (float*)d_out;

    pre_small<<<ZN, 128>>>(geo, feat, W1, b2);
    pre_G<<<ZN / PTS, 256>>>(feat, W2);
    pair_kernel<<<ZN, 256>>>(b1, out);
}

// round 2
// speedup vs baseline: 1.4134x; 1.4134x over previous
#include <cuda_runtime.h>
#include <cstdint>

#define Z 4
#define N 256
#define CIN 32
#define COUT 32
#define HID 64
#define ZN (Z * N)
#define GSZ (HID * COUT)   // 2048 per point

// Scratch (no cudaMalloc allowed)
__device__ float g_Ub[ZN * HID];          // U + b1, row layout [p][h]   (Ub side)
__device__ float g_UT[Z * HID * N];       // U transposed [z][h][a]      (Ua side)
__device__ float g_G[(size_t)ZN * GSZ];   // [p][h][i]
__device__ float g_Bf[ZN * COUT];         // [p][i]

// ---------------------------------------------------------------------------
// Fused precompute: U (+b1), U^T, Bf, G.  64 blocks x 256 threads.
// W2 (256KB) is streamed once per block (16 points) -> 16MB L2 traffic total.
// ---------------------------------------------------------------------------
#define PTS 16
__global__ void __launch_bounds__(256) pre_all(
    const float* __restrict__ geo, const float* __restrict__ feat,
    const float* __restrict__ W1, const float* __restrict__ b1,
    const float* __restrict__ W2, const float* __restrict__ b2) {
    int pbase = blockIdx.x * PTS;
    int t = threadIdx.x;
    __shared__ float4 fs4[PTS][CIN / 4];   // [16][8]
    __shared__ float g3s[PTS][3];
    if (t < PTS * (CIN / 4)) {
        int p = t >> 3, j4 = t & 7;
        fs4[p][j4] = ((const float4*)feat)[(size_t)(pbase + p) * (CIN / 4) + j4];
    }
    if (t >= 128 && t < 128 + PTS * 3) {
        int q = t - 128;
        g3s[q / 3][q % 3] = geo[(pbase + q / 3) * 3 + (q % 3)];
    }
    __syncthreads();

    // U: 16 points x 64 h = 1024 entries, 4 per thread
    #pragma unroll
    for (int k = 0; k < 4; ++k) {
        int idx = t + k * 256;
        int pl = idx >> 6, h = idx & 63;
        int p = pbase + pl;
        float u = g3s[pl][0] * W1[h] + g3s[pl][1] * W1[HID + h]
                + g3s[pl][2] * W1[2 * HID + h];
        g_Ub[p * HID + h] = u + b1[h];
        int z = p >> 8, a = p & 255;
        g_UT[(z * HID + h) * N + a] = u;
    }

    // Bf: 16 x 32 = 512 entries, 2 per thread
    #pragma unroll
    for (int k = 0; k < 2; ++k) {
        int idx = t + k * 256;
        int pl = idx >> 5, i = idx & 31;
        const float4* b4 = (const float4*)(b2 + i * CIN);
        float s = 0.f;
        #pragma unroll
        for (int j4 = 0; j4 < 8; ++j4) {
            float4 w = b4[j4]; float4 f = fs4[pl][j4];
            s += w.x * f.x + w.y * f.y + w.z * f.z + w.w * f.w;
        }
        g_Bf[(pbase + pl) * COUT + i] = s;
    }

    // G[p][h][i] = sum_j W2[h, i*32+j] * f[p][j]
    for (int e = t; e < GSZ; e += 256) {
        int h = e >> 5, i = e & 31;
        const float4* wrow = (const float4*)(W2 + (size_t)h * (COUT * CIN) + i * CIN);
        float4 w[8];
        #pragma unroll
        for (int j4 = 0; j4 < 8; ++j4) w[j4] = wrow[j4];
        float acc[PTS];
        #pragma unroll
        for (int p = 0; p < PTS; ++p) acc[p] = 0.f;
        #pragma unroll
        for (int j4 = 0; j4 < 8; ++j4) {
            #pragma unroll
            for (int p = 0; p < PTS; ++p) {
                float4 fv = fs4[p][j4];
                acc[p] += w[j4].x * fv.x + w[j4].y * fv.y
                        + w[j4].z * fv.z + w[j4].w * fv.w;
            }
        }
        #pragma unroll
        for (int p = 0; p < PTS; ++p)
            g_G[(size_t)(pbase + p) * GSZ + e] = acc[p];
    }
}

// ---------------------------------------------------------------------------
// Pair kernel v2: register-tiled. One block per (z,b).
// 128 threads, thread tile = 8a x 8i  (C[256x32] = relu(H)[256x64] x G[64x32]).
// H computed once per block into smem (two 32-h halves to keep smem at 40KB).
// Inner step: 32B H + 32B G loaded per thread -> 32 FFMA2.
// ---------------------------------------------------------------------------
__global__ void __launch_bounds__(128) pair_kernel(float* __restrict__ out) {
    int p = blockIdx.x;          // z*N + b
    int z = p >> 8;
    int b = p & 255;
    int t = threadIdx.x;
    int ti = t & 3;              // i-group: i_base = ti*8
    int ta = t >> 2;             // a-group: a_base = ta*8
    int i_base = ti * 8;
    int a_base = ta * 8;

    __shared__ float Gs[GSZ];        // 8 KB
    __shared__ float Hs[32][N];      // 32 KB (one 32-h half at a time)

    // Load G tile (coalesced float4, 4 per thread)
    {
        const float4* src = (const float4*)(g_G + (size_t)p * GSZ);
        float4* dst = (float4*)Gs;
        #pragma unroll
        for (int k = 0; k < 4; ++k) dst[t + 128 * k] = src[t + 128 * k];
    }

    // acc[8 a-rows][2 x ulonglong2] = 8x8 fp32 outputs, init with Bf
    ulonglong2 acc[8][2];
    {
        const ulonglong2* bf = (const ulonglong2*)(g_Bf + p * COUT + i_base);
        ulonglong2 b0 = bf[0], b1v = bf[1];
        #pragma unroll
        for (int r = 0; r < 8; ++r) { acc[r][0] = b0; acc[r][1] = b1v; }
    }

    const float* Ubp = g_Ub + p * HID;

    #pragma unroll
    for (int half = 0; half < 2; ++half) {
        __syncthreads();   // protect Hs from previous half's readers (and Gs for half 0)
        // Fill Hs for h in [half*32, half*32+32): 32x64 float4, 16 per thread.
        #pragma unroll
        for (int k = 0; k < 16; ++k) {
            int idx = t + k * 128;
            int hl = idx >> 6;        // 0..31
            int a4 = idx & 63;        // float4 index over a
            float ub = Ubp[half * 32 + hl];            // warp-uniform LDG
            float4 u = ((const float4*)(g_UT + (size_t)(z * HID + half * 32 + hl) * N))[a4];
            float4 hv;
            hv.x = fmaxf(ub - u.x, 0.f);
            hv.y = fmaxf(ub - u.y, 0.f);
            hv.z = fmaxf(ub - u.z, 0.f);
            hv.w = fmaxf(ub - u.w, 0.f);
            ((float4*)Hs[hl])[a4] = hv;
        }
        __syncthreads();

        #pragma unroll 8
        for (int hh = 0; hh < 32; ++hh) {
            const float4* hp = (const float4*)(Hs[hh] + a_base);
            float4 hv0 = hp[0];
            float4 hv1 = hp[1];
            const ulonglong2* gp =
                (const ulonglong2*)(Gs + (half * 32 + hh) * COUT + i_base);
            ulonglong2 g0 = gp[0];
            ulonglong2 g1 = gp[1];
            float hv[8] = {hv0.x, hv0.y, hv0.z, hv0.w, hv1.x, hv1.y, hv1.z, hv1.w};
            #pragma unroll
            for (int r = 0; r < 8; ++r) {
                unsigned long long s;
                unsigned int hb = __float_as_uint(hv[r]);
                asm("mov.b64 %0, {%1, %1};" : "=l"(s) : "r"(hb));
                asm("fma.rn.f32x2 %0, %1, %2, %0;" : "+l"(acc[r][0].x) : "l"(s), "l"(g0.x));
                asm("fma.rn.f32x2 %0, %1, %2, %0;" : "+l"(acc[r][0].y) : "l"(s), "l"(g0.y));
                asm("fma.rn.f32x2 %0, %1, %2, %0;" : "+l"(acc[r][1].x) : "l"(s), "l"(g1.x));
                asm("fma.rn.f32x2 %0, %1, %2, %0;" : "+l"(acc[r][1].y) : "l"(s), "l"(g1.y));
            }
        }
    }

    // Store: 8 rows x 32B each (2 STG.128 per row), i contiguous.
    #pragma unroll
    for (int r = 0; r < 8; ++r) {
        size_t o = (((size_t)(z * N + a_base + r)) * N + b) * COUT + i_base;
        ulonglong2* o2 = (ulonglong2*)(out + o);
        o2[0] = acc[r][0];
        o2[1] = acc[r][1];
    }
}

// ---------------------------------------------------------------------------
extern "C" void kernel_launch(void* const* d_in, const int* in_sizes, int n_in,
                              void* d_out, int out_size) {
    const float* feat = (const float*)d_in[0];
    const float* geo  = (const float*)d_in[1];
    const float* W1   = (const float*)d_in[2];
    const float* b1   = (const float*)d_in[3];
    const float* W2   = (const float*)d_in[4];
    const float* b2   = (const float*)d_in[5];
    float* out = (float*)d_out;

    pre_all<<<ZN / PTS, 256>>>(geo, feat, W1, b1, W2, b2);
    pair_kernel<<<ZN, 128>>>(out);
}

// round 3
// speedup vs baseline: 2.2283x; 1.5766x over previous
#include <cuda_runtime.h>
#include <cstdint>

#define Z 4
#define N 256
#define CIN 32
#define COUT 32
#define HID 64
#define ZN (Z * N)
#define GSZ (HID * COUT)   // 2048

// Scratch (no cudaMalloc allowed)
__device__ float g_Ub[ZN * HID];          // U + b1, [p][h]
__device__ float g_UT[Z * HID * N];       // U transposed [z][h][a]
__device__ float g_G[(size_t)ZN * GSZ];   // [p][h*32+i]
__device__ float g_Bf[ZN * COUT];         // [p][i]

// ---------------------------------------------------------------------------
// pre1: U (+b1), U^T, Bf.  64 blocks x 256 threads, 16 points/block.
// ---------------------------------------------------------------------------
#define PTS 16
__global__ void __launch_bounds__(256) pre1(
    const float* __restrict__ geo, const float* __restrict__ feat,
    const float* __restrict__ W1, const float* __restrict__ b1,
    const float* __restrict__ b2) {
    int pbase = blockIdx.x * PTS;
    int t = threadIdx.x;
    __shared__ float4 fs4[PTS][CIN / 4];
    __shared__ float g3s[PTS][3];
    if (t < PTS * (CIN / 4)) {
        int p = t >> 3, j4 = t & 7;
        fs4[p][j4] = ((const float4*)feat)[(size_t)(pbase + p) * (CIN / 4) + j4];
    }
    if (t >= 128 && t < 128 + PTS * 3) {
        int q = t - 128;
        g3s[q / 3][q % 3] = geo[(pbase + q / 3) * 3 + (q % 3)];
    }
    __syncthreads();

    #pragma unroll
    for (int k = 0; k < 4; ++k) {
        int idx = t + k * 256;
        int pl = idx >> 6, h = idx & 63;
        int p = pbase + pl;
        float u = g3s[pl][0] * W1[h] + g3s[pl][1] * W1[HID + h]
                + g3s[pl][2] * W1[2 * HID + h];
        g_Ub[p * HID + h] = u + b1[h];
        int z = p >> 8, a = p & 255;
        g_UT[(z * HID + h) * N + a] = u;
    }

    #pragma unroll
    for (int k = 0; k < 2; ++k) {
        int idx = t + k * 256;
        int pl = idx >> 5, i = idx & 31;
        const float4* b4 = (const float4*)(b2 + i * CIN);
        float s = 0.f;
        #pragma unroll
        for (int j4 = 0; j4 < 8; ++j4) {
            float4 w = b4[j4]; float4 f = fs4[pl][j4];
            s += w.x * f.x + w.y * f.y + w.z * f.z + w.w * f.w;
        }
        g_Bf[(pbase + pl) * COUT + i] = s;
    }
}

// ---------------------------------------------------------------------------
// pre2: SGEMM  G[1024 x 2048] = feat[1024 x 32] * Wre[32 x 2048]
//   Wre[j][h*32+i] = W2[h][i*32+j]
// Block tile 64p x 256e, grid (16,8).  256 threads, thread tile 8p x 8e.
// Warp layout: lanes span p-groups (pg=t&7), e-group per 8-lane cluster ->
// W frags contiguous-128B conflict-free; F loads 4-bank 2-way (cheap).
// ---------------------------------------------------------------------------
#define FS_PAD 33
#define WS_PAD 264
__global__ void __launch_bounds__(256) pre2(
    const float* __restrict__ feat, const float* __restrict__ W2) {
    int pbase = blockIdx.x * 64;
    int eb = blockIdx.y * 256;
    int h0 = eb >> 5;                 // 8 h-rows per block
    int t = threadIdx.x;
    int pg = t & 7, eg = t >> 3;      // p0 = pg*8, e0 = eg*8
    int p0 = pg * 8, e0 = eg * 8;

    __shared__ float Fs[64 * FS_PAD];       // 8.25 KB
    __shared__ float Ws[32][WS_PAD];        // 33 KB (rows 16B-aligned: 264*4%16==0)

    // Fill Fs (coalesced LDG.32, conflict-free STS)
    #pragma unroll
    for (int k = 0; k < 8; ++k) {
        int idx = t + k * 256;
        int p = idx >> 5, j = idx & 31;
        Fs[p * FS_PAD + j] = feat[(pbase + p) * 32 + j];
    }
    // Fill Ws: gather-transpose of W2 tile. lane j4 covers j, coalesced LDG.128.
    {
        int lane = t & 31, w = t >> 5;
        int j4 = lane & 7, sub = lane >> 3;
        #pragma unroll
        for (int q = 0; q < 8; ++q) {
            int hi = w * 32 + q * 4 + sub;     // 0..255 (h,i) pairs
            int hl = hi >> 5, i = hi & 31;
            float4 v = ((const float4*)W2)[(size_t)((h0 + hl) * (COUT * CIN) + i * CIN) / 4 + j4];
            int e = hl * 32 + i;
            Ws[j4 * 4 + 0][e] = v.x;
            Ws[j4 * 4 + 1][e] = v.y;
            Ws[j4 * 4 + 2][e] = v.z;
            Ws[j4 * 4 + 3][e] = v.w;
        }
    }
    __syncthreads();

    ulonglong2 acc[8][2];
    #pragma unroll
    for (int r = 0; r < 8; ++r) {
        acc[r][0].x = 0ull; acc[r][0].y = 0ull;
        acc[r][1].x = 0ull; acc[r][1].y = 0ull;
    }

    #pragma unroll 8
    for (int j = 0; j < 32; ++j) {
        ulonglong2 w0 = *(const ulonglong2*)&Ws[j][e0];
        ulonglong2 w1 = *(const ulonglong2*)&Ws[j][e0 + 4];
        #pragma unroll
        for (int r = 0; r < 8; ++r) {
            float f = Fs[(p0 + r) * FS_PAD + j];
            unsigned long long s;
            unsigned int fb = __float_as_uint(f);
            asm("mov.b64 %0, {%1, %1};" : "=l"(s) : "r"(fb));
            asm("fma.rn.f32x2 %0, %1, %2, %0;" : "+l"(acc[r][0].x) : "l"(s), "l"(w0.x));
            asm("fma.rn.f32x2 %0, %1, %2, %0;" : "+l"(acc[r][0].y) : "l"(s), "l"(w0.y));
            asm("fma.rn.f32x2 %0, %1, %2, %0;" : "+l"(acc[r][1].x) : "l"(s), "l"(w1.x));
            asm("fma.rn.f32x2 %0, %1, %2, %0;" : "+l"(acc[r][1].y) : "l"(s), "l"(w1.y));
        }
    }

    #pragma unroll
    for (int r = 0; r < 8; ++r) {
        float* dst = g_G + (size_t)(pbase + p0 + r) * GSZ + eb + e0;
        ((ulonglong2*)dst)[0] = acc[r][0];
        ((ulonglong2*)dst)[1] = acc[r][1];
    }
}

// ---------------------------------------------------------------------------
// pair v3: one block per (z,b). 128 threads, thread tile = (4+4)a x 8i.
// Each thread's a-rows: {ta*4..+3} and {128+ta*4..+3} so every H LDS.128
// wavefront is a contiguous 128B region (conflict-free, RF-write bound only).
// ---------------------------------------------------------------------------
__global__ void __launch_bounds__(128, 4) pair_kernel(float* __restrict__ out) {
    int p = blockIdx.x;
    int z = p >> 8;
    int b = p & 255;
    int t = threadIdx.x;
    int ti = t & 3, ta = t >> 2;
    int i0 = ti * 8;
    int aA = ta * 4;
    int aB = 128 + ta * 4;

    __shared__ float Gs[GSZ];       // 8 KB
    __shared__ float Hs[32][N];     // 32 KB

    {
        const float4* gsrc = (const float4*)(g_G + (size_t)p * GSZ);
        float4* gdst = (float4*)Gs;
        #pragma unroll
        for (int k = 0; k < 4; ++k) gdst[t + 128 * k] = gsrc[t + 128 * k];
    }

    ulonglong2 acc[8][2];
    {
        const ulonglong2* bf = (const ulonglong2*)(g_Bf + p * COUT + i0);
        ulonglong2 c0 = bf[0], c1 = bf[1];
        #pragma unroll
        for (int r = 0; r < 8; ++r) { acc[r][0] = c0; acc[r][1] = c1; }
    }

    const float* Ubp = g_Ub + p * HID;

    #pragma unroll
    for (int half = 0; half < 2; ++half) {
        __syncthreads();
        #pragma unroll
        for (int k = 0; k < 16; ++k) {
            int idx = t + k * 128;
            int hl = idx >> 6;
            int a4 = idx & 63;
            float ub = Ubp[half * 32 + hl];
            float4 u = ((const float4*)(g_UT + (size_t)(z * HID + half * 32 + hl) * N))[a4];
            float4 hv;
            hv.x = fmaxf(ub - u.x, 0.f);
            hv.y = fmaxf(ub - u.y, 0.f);
            hv.z = fmaxf(ub - u.z, 0.f);
            hv.w = fmaxf(ub - u.w, 0.f);
            ((float4*)Hs[hl])[a4] = hv;
        }
        __syncthreads();

        #pragma unroll 8
        for (int hh = 0; hh < 32; ++hh) {
            float4 hA = *(const float4*)&Hs[hh][aA];
            float4 hB = *(const float4*)&Hs[hh][aB];
            const ulonglong2* gp =
                (const ulonglong2*)(Gs + (half * 32 + hh) * COUT + i0);
            ulonglong2 g0 = gp[0];
            ulonglong2 g1 = gp[1];
            float hv[8] = {hA.x, hA.y, hA.z, hA.w, hB.x, hB.y, hB.z, hB.w};
            #pragma unroll
            for (int r = 0; r < 8; ++r) {
                unsigned long long s;
                unsigned int hb = __float_as_uint(hv[r]);
                asm("mov.b64 %0, {%1, %1};" : "=l"(s) : "r"(hb));
                asm("fma.rn.f32x2 %0, %1, %2, %0;" : "+l"(acc[r][0].x) : "l"(s), "l"(g0.x));
                asm("fma.rn.f32x2 %0, %1, %2, %0;" : "+l"(acc[r][0].y) : "l"(s), "l"(g0.y));
                asm("fma.rn.f32x2 %0, %1, %2, %0;" : "+l"(acc[r][1].x) : "l"(s), "l"(g1.x));
                asm("fma.rn.f32x2 %0, %1, %2, %0;" : "+l"(acc[r][1].y) : "l"(s), "l"(g1.y));
            }
        }
    }

    #pragma unroll
    for (int r = 0; r < 8; ++r) {
        int a = (r < 4) ? (aA + r) : (aB + (r - 4));
        size_t o = (((size_t)(z * N + a)) * N + b) * COUT + i0;
        ulonglong2* o2 = (ulonglong2*)(out + o);
        o2[0] = acc[r][0];
        o2[1] = acc[r][1];
    }
}

// ---------------------------------------------------------------------------
extern "C" void kernel_launch(void* const* d_in, const int* in_sizes, int n_in,
                              void* d_out, int out_size) {
    const float* feat = (const float*)d_in[0];
    const float* geo  = (const float*)d_in[1];
    const float* W1   = (const float*)d_in[2];
    const float* b1   = (const float*)d_in[3];
    const float* W2   = (const float*)d_in[4];
    const float* b2   = (const float*)d_in[5];
    float* out = (float*)d_out;

    pre1<<<ZN / PTS, 256>>>(geo, feat, W1, b1, b2);
    pre2<<<dim3(16, 8), 256>>>(feat, W2);
    pair_kernel<<<ZN, 128>>>(out);
}

// round 6
// speedup vs baseline: 2.7272x; 1.2239x over previous
#include <cuda_runtime.h>
#include <cstdint>

#define NPTS 1024
#define HID 64
#define COUT 32

// Scratch (no cudaMalloc allowed)
__device__ float g_U [NPTS * HID];            // raw U rows [p][h]
__device__ float g_Ub[NPTS * HID];            // U + b1    [p][h]
__device__ float g_Bf[NPTS * COUT];           // [p][i]
__device__ float g_G [NPTS * COUT * HID];     // [p][i][h]

// ===========================================================================
// warp-level tf32 mma (baseline PTX, sm_80+; runs on Blackwell fallback HMMA)
// ===========================================================================
__device__ __forceinline__ void mma8(float* c, const uint32_t* a,
                                     uint32_t bb0, uint32_t bb1) {
    asm("mma.sync.aligned.m16n8k8.row.col.f32.tf32.tf32.f32 "
        "{%0,%1,%2,%3}, {%4,%5,%6,%7}, {%8,%9}, {%0,%1,%2,%3};"
        : "+f"(c[0]), "+f"(c[1]), "+f"(c[2]), "+f"(c[3])
        : "r"(a[0]), "r"(a[1]), "r"(a[2]), "r"(a[3]), "r"(bb0), "r"(bb1));
}

__device__ __forceinline__ uint32_t tf32_hi(float x) {
    return __float_as_uint(x) & 0xFFFFE000u;
}

// ===========================================================================
// Fused precompute (grid 16x8, 256 thr):  U/Ub/Bf (8 pts/blk) + G SGEMM
//   G[p][i*64+h] = sum_j W2[h][i*32+j] * feat[p][j]
// ===========================================================================
#define FS_PAD 33
__global__ void __launch_bounds__(256) pre_all(
    const float* __restrict__ geo, const float* __restrict__ feat,
    const float* __restrict__ W1, const float* __restrict__ b1,
    const float* __restrict__ W2, const float* __restrict__ b2) {
    int bx = blockIdx.x, by = blockIdx.y;
    int t = threadIdx.x;

    {   // U, Ub, Bf for 8 points
        int pb = (by * 16 + bx) * 8;
        #pragma unroll
        for (int k = 0; k < 2; ++k) {
            int idx = t + k * 256;
            int pl = idx >> 6, h = idx & 63;
            int p = pb + pl;
            float gx = geo[p * 3], gy = geo[p * 3 + 1], gz = geo[p * 3 + 2];
            float u = gx * W1[h] + gy * W1[64 + h] + gz * W1[128 + h];
            g_U[p * 64 + h] = u;
            g_Ub[p * 64 + h] = u + b1[h];
        }
        int pl = t >> 5, i = t & 31;
        const float4* bw = (const float4*)(b2 + i * 32);
        const float4* fv = (const float4*)(feat + (size_t)(pb + pl) * 32);
        float s = 0.f;
        #pragma unroll
        for (int j = 0; j < 8; ++j) {
            float4 w = bw[j], f = fv[j];
            s += w.x * f.x + w.y * f.y + w.z * f.z + w.w * f.w;
        }
        g_Bf[(pb + pl) * 32 + i] = s;
    }

    // G SGEMM, block tile 64p x 256e, e = i_l*64 + h
    int pbase = bx * 64;
    int i0g = by * 4;
    int pg = t & 7, eg = t >> 3;
    int p0 = pg * 8, e0 = eg * 8;

    __shared__ float Fs[64 * FS_PAD];
    __shared__ float Ws[32][264];

    #pragma unroll
    for (int k = 0; k < 8; ++k) {
        int idx = t + k * 256;
        int p = idx >> 5, j = idx & 31;
        Fs[p * FS_PAD + j] = feat[(size_t)(pbase + p) * 32 + j];
    }
    {
        int lane = t & 31, w = t >> 5;
        int j4 = lane & 7, sub = lane >> 3;
        #pragma unroll
        for (int q = 0; q < 8; ++q) {
            int pidx = w * 32 + q * 4 + sub;
            int il = pidx >> 6, h = pidx & 63;
            float4 v = ((const float4*)W2)[((size_t)h * 1024 + (i0g + il) * 32) / 4 + j4];
            int e = il * 64 + h;
            Ws[j4 * 4 + 0][e] = v.x;
            Ws[j4 * 4 + 1][e] = v.y;
            Ws[j4 * 4 + 2][e] = v.z;
            Ws[j4 * 4 + 3][e] = v.w;
        }
    }
    __syncthreads();

    ulonglong2 acc[8][2];
    #pragma unroll
    for (int r = 0; r < 8; ++r) {
        acc[r][0].x = acc[r][0].y = 0ull;
        acc[r][1].x = acc[r][1].y = 0ull;
    }
    #pragma unroll 8
    for (int j = 0; j < 32; ++j) {
        ulonglong2 w0 = *(const ulonglong2*)&Ws[j][e0];
        ulonglong2 w1 = *(const ulonglong2*)&Ws[j][e0 + 4];
        #pragma unroll
        for (int r = 0; r < 8; ++r) {
            float f = Fs[(p0 + r) * FS_PAD + j];
            unsigned long long s;
            unsigned int fb = __float_as_uint(f);
            asm("mov.b64 %0, {%1, %1};" : "=l"(s) : "r"(fb));
            asm("fma.rn.f32x2 %0, %1, %2, %0;" : "+l"(acc[r][0].x) : "l"(s), "l"(w0.x));
            asm("fma.rn.f32x2 %0, %1, %2, %0;" : "+l"(acc[r][0].y) : "l"(s), "l"(w0.y));
            asm("fma.rn.f32x2 %0, %1, %2, %0;" : "+l"(acc[r][1].x) : "l"(s), "l"(w1.x));
            asm("fma.rn.f32x2 %0, %1, %2, %0;" : "+l"(acc[r][1].y) : "l"(s), "l"(w1.y));
        }
    }
    #pragma unroll
    for (int r = 0; r < 8; ++r) {
        float* dst = g_G + (size_t)(pbase + p0 + r) * 2048 + by * 256 + e0;
        ((ulonglong2*)dst)[0] = acc[r][0];
        ((ulonglong2*)dst)[1] = acc[r][1];
    }
}

// ===========================================================================
// Pair kernel: warp-level tf32 MMA. One block per (z,b), 256 threads (8 warps).
// C[256x32] = relu(H)[256x64] * G^T in two 128-row halves; warp w owns strip w.
// Smem (floats): Us[128*68] | Gh[32*68] | Gl[32*68] | Ss[128*36] | Ub[64] | Bf[32]
// ===========================================================================
#define PU 68
#define PS 36
#define OFF_US 0
#define OFF_GH (128 * PU)                 // 8704
#define OFF_GL (OFF_GH + 32 * PU)         // 10880
#define OFF_SS (OFF_GL + 32 * PU)         // 13056
#define OFF_UB (OFF_SS + 128 * PS)        // 17664
#define OFF_BF (OFF_UB + 64)              // 17728
#define SM_FLOATS (OFF_BF + 32)           // 17760 floats = 71040 B

__global__ void __launch_bounds__(256) pair_kernel(float* __restrict__ out) {
    extern __shared__ float sm[];
    float* Us = sm + OFF_US;
    float* Gh = sm + OFF_GH;
    float* Gl = sm + OFF_GL;
    float* Ss = sm + OFF_SS;
    float* Ub = sm + OFF_UB;
    float* Bf = sm + OFF_BF;

    int p = blockIdx.x, z = p >> 8, b = p & 255;
    int t = threadIdx.x;
    int lane = t & 31, wid = t >> 5;
    int g = lane >> 2, tid = lane & 3;

    // ---- fills: Ub, Bf, G(split), Us half 0 ----
    if (t < 64) Ub[t] = g_Ub[p * 64 + t];
    else if (t < 96) Bf[t - 64] = g_Bf[p * 32 + (t - 64)];

    #pragma unroll
    for (int it = 0; it < 2; ++it) {
        int idx = it * 256 + t;                 // 512 float4 = 32 i x 16 h4
        int i = idx >> 4, h4 = idx & 15;
        float4 gv = ((const float4*)(g_G + (size_t)p * 2048))[idx];
        float4 hi4, lo4;
        hi4.x = __uint_as_float(tf32_hi(gv.x)); lo4.x = gv.x - hi4.x;
        hi4.y = __uint_as_float(tf32_hi(gv.y)); lo4.y = gv.y - hi4.y;
        hi4.z = __uint_as_float(tf32_hi(gv.z)); lo4.z = gv.z - hi4.z;
        hi4.w = __uint_as_float(tf32_hi(gv.w)); lo4.w = gv.w - hi4.w;
        ((float4*)(Gh + i * PU))[h4] = hi4;
        ((float4*)(Gl + i * PU))[h4] = lo4;
    }
    #pragma unroll
    for (int it = 0; it < 8; ++it) {            // Us half 0: 128 rows x 16 h4
        int idx = it * 256 + t;
        int row = idx >> 4, h4 = idx & 15;
        float4 u = ((const float4*)g_U)[(size_t)(z * 256 + row) * 16 + h4];
        ((float4*)(Us + row * PU))[h4] = u;
    }
    __syncthreads();

    // Ub fragments: col = tid + 4j
    float ubf[16];
    #pragma unroll
    for (int j = 0; j < 16; ++j) ubf[j] = Ub[tid + 4 * j];

    #pragma unroll
    for (int half = 0; half < 2; ++half) {
        // ---- mainloop: warp 'wid' computes m16 strip 'wid' ----
        float acc[4][4];
        #pragma unroll
        for (int n = 0; n < 4; ++n)
            acc[n][0] = acc[n][1] = acc[n][2] = acc[n][3] = 0.f;

        const float* ua0 = Us + (wid * 16 + g) * PU;
        const float* ua1 = ua0 + 8 * PU;

        #pragma unroll
        for (int k = 0; k < 8; ++k) {
            float x0 = ua0[8 * k + tid], x1 = ua0[8 * k + tid + 4];
            float y0 = ua1[8 * k + tid], y1 = ua1[8 * k + tid + 4];
            float h0 = fmaxf(ubf[2 * k] - x0, 0.f);
            float h1 = fmaxf(ubf[2 * k] - y0, 0.f);
            float h2 = fmaxf(ubf[2 * k + 1] - x1, 0.f);
            float h3 = fmaxf(ubf[2 * k + 1] - y1, 0.f);
            uint32_t ahi[4], alo[4];
            ahi[0] = tf32_hi(h0); alo[0] = __float_as_uint(h0 - __uint_as_float(ahi[0]));
            ahi[1] = tf32_hi(h1); alo[1] = __float_as_uint(h1 - __uint_as_float(ahi[1]));
            ahi[2] = tf32_hi(h2); alo[2] = __float_as_uint(h2 - __uint_as_float(ahi[2]));
            ahi[3] = tf32_hi(h3); alo[3] = __float_as_uint(h3 - __uint_as_float(ahi[3]));
            #pragma unroll
            for (int n = 0; n < 4; ++n) {
                const float* gh = Gh + (n * 8 + g) * PU + 8 * k + tid;
                const float* gl = Gl + (n * 8 + g) * PU + 8 * k + tid;
                uint32_t b0h = __float_as_uint(gh[0]), b1h = __float_as_uint(gh[4]);
                uint32_t b0l = __float_as_uint(gl[0]), b1l = __float_as_uint(gl[4]);
                mma8(acc[n], ahi, b0h, b1h);
                mma8(acc[n], ahi, b0l, b1l);
                mma8(acc[n], alo, b0h, b1h);
            }
        }

        // ---- stage C into Ss (each warp writes only its own 16 rows) ----
        {
            float* s0 = Ss + (wid * 16 + g) * PS;
            float* s1 = s0 + 8 * PS;
            #pragma unroll
            for (int n = 0; n < 4; ++n) {
                int c = n * 8 + 2 * tid;
                s0[c] = acc[n][0]; s0[c + 1] = acc[n][1];
                s1[c] = acc[n][2]; s1[c + 1] = acc[n][3];
            }
        }
        __syncthreads();

        // ---- coalesced epilogue (+Bf) and Us refill for next half ----
        #pragma unroll
        for (int it = 0; it < 4; ++it) {
            int idx = it * 256 + t;                 // 128 rows x 8 col4
            int row = idx >> 3, c4 = idx & 7;
            float4 v = ((const float4*)(Ss + row * PS))[c4];
            float4 bf4 = ((const float4*)Bf)[c4];
            v.x += bf4.x; v.y += bf4.y; v.z += bf4.z; v.w += bf4.w;
            int a = half * 128 + row;
            ((float4*)(out + (((size_t)(z * 256 + a)) * 256 + b) * 32))[c4] = v;
        }
        if (half == 0) {
            #pragma unroll
            for (int it = 0; it < 8; ++it) {        // Us half 1
                int idx = it * 256 + t;
                int row = idx >> 4, h4 = idx & 15;
                float4 u = ((const float4*)g_U)[(size_t)(z * 256 + 128 + row) * 16 + h4];
                ((float4*)(Us + row * PU))[h4] = u;
            }
        }
        __syncthreads();
    }
}

// ===========================================================================
extern "C" void kernel_launch(void* const* d_in, const int* in_sizes, int n_in,
                              void* d_out, int out_size) {
    const float* feat = (const float*)d_in[0];
    const float* geo  = (const float*)d_in[1];
    const float* W1   = (const float*)d_in[2];
    const float* b1   = (const float*)d_in[3];
    const float* W2   = (const float*)d_in[4];
    const float* b2   = (const float*)d_in[5];
    float* out = (float*)d_out;

    cudaFuncSetAttribute(pair_kernel, cudaFuncAttributeMaxDynamicSharedMemorySize,
                         SM_FLOATS * 4);

    pre_all<<<dim3(16, 8), 256>>>(geo, feat, W1, b1, W2, b2);
    pair_kernel<<<NPTS, 256, SM_FLOATS * 4>>>(out);
}

// round 7
// speedup vs baseline: 3.1655x; 1.1607x over previous
#include <cuda_runtime.h>
#include <cstdint>

#define NPTS 1024

// Scratch (no cudaMalloc allowed)
__device__ float    g_UT[4 * 64 * 256];        // [z][h][a]  raw U transposed
__device__ float    g_Ub[NPTS * 64];           // U + b1 [p][h]
__device__ float    g_Bf[NPTS * 32];           // [p][i]
__device__ uint32_t g_Gh[NPTS * 32 * 32];      // bf16x2 hi  [p][i][k2]
__device__ uint32_t g_Gm[NPTS * 32 * 32];      // bf16x2 mid [p][i][k2]

// ===========================================================================
// helpers
// ===========================================================================
__device__ __forceinline__ uint32_t bf16x2_of(float lo, float hi) {
    uint32_t r;
    asm("cvt.rn.bf16x2.f32 %0, %1, %2;" : "=r"(r) : "f"(hi), "f"(lo));
    return r;
}
__device__ __forceinline__ float bf_lo(uint32_t p) { return __uint_as_float(p << 16); }
__device__ __forceinline__ float bf_hi(uint32_t p) { return __uint_as_float(p & 0xFFFF0000u); }

__device__ __forceinline__ void split_u64(unsigned long long v, uint32_t& ph, uint32_t& pm) {
    float lo = __uint_as_float((uint32_t)v);
    float hi = __uint_as_float((uint32_t)(v >> 32));
    ph = bf16x2_of(lo, hi);
    pm = bf16x2_of(lo - bf_lo(ph), hi - bf_hi(ph));
}

__device__ __forceinline__ void mma_bf16(float* c, uint32_t a0, uint32_t a1,
                                         uint32_t a2, uint32_t a3,
                                         uint32_t b0, uint32_t b1) {
    asm("mma.sync.aligned.m16n8k16.row.col.f32.bf16.bf16.f32 "
        "{%0,%1,%2,%3},{%4,%5,%6,%7},{%8,%9},{%0,%1,%2,%3};"
        : "+f"(c[0]), "+f"(c[1]), "+f"(c[2]), "+f"(c[3])
        : "r"(a0), "r"(a1), "r"(a2), "r"(a3), "r"(b0), "r"(b1));
}

// ===========================================================================
// Fused precompute (grid 16x8, 256 thr):  UT/Ub/Bf (8 pts/blk) + G SGEMM
//   G[p][i][h] = sum_j W2[h][i*32+j] * feat[p][j]  -> bf16 hi/mid packed
// ===========================================================================
#define FS_PAD 33
__global__ void __launch_bounds__(256) pre_all(
    const float* __restrict__ geo, const float* __restrict__ feat,
    const float* __restrict__ W1, const float* __restrict__ b1,
    const float* __restrict__ W2, const float* __restrict__ b2) {
    int bx = blockIdx.x, by = blockIdx.y;
    int t = threadIdx.x;

    {   // U(->transposed), Ub, Bf for 8 points
        int pb = (by * 16 + bx) * 8;
        #pragma unroll
        for (int k = 0; k < 2; ++k) {
            int idx = t + k * 256;
            int pl = idx >> 6, h = idx & 63;
            int p = pb + pl;
            float gx = geo[p * 3], gy = geo[p * 3 + 1], gz = geo[p * 3 + 2];
            float u = gx * W1[h] + gy * W1[64 + h] + gz * W1[128 + h];
            int z = p >> 8, a = p & 255;
            g_UT[(z * 64 + h) * 256 + a] = u;
            g_Ub[p * 64 + h] = u + b1[h];
        }
        int pl = t >> 5, i = t & 31;
        const float4* bw = (const float4*)(b2 + i * 32);
        const float4* fv = (const float4*)(feat + (size_t)(pb + pl) * 32);
        float s = 0.f;
        #pragma unroll
        for (int j = 0; j < 8; ++j) {
            float4 w = bw[j], f = fv[j];
            s += w.x * f.x + w.y * f.y + w.z * f.z + w.w * f.w;
        }
        g_Bf[(pb + pl) * 32 + i] = s;
    }

    // G SGEMM, block tile 64p x 256e, e = i_l*64 + h
    int pbase = bx * 64;
    int i0g = by * 4;
    int pg = t & 7, eg = t >> 3;
    int p0 = pg * 8, e0 = eg * 8;

    __shared__ float Fs[64 * FS_PAD];
    __shared__ float Ws[32][264];

    #pragma unroll
    for (int k = 0; k < 8; ++k) {
        int idx = t + k * 256;
        int p = idx >> 5, j = idx & 31;
        Fs[p * FS_PAD + j] = feat[(size_t)(pbase + p) * 32 + j];
    }
    {
        int lane = t & 31, w = t >> 5;
        int j4 = lane & 7, sub = lane >> 3;
        #pragma unroll
        for (int q = 0; q < 8; ++q) {
            int pidx = w * 32 + q * 4 + sub;
            int il = pidx >> 6, h = pidx & 63;
            float4 v = ((const float4*)W2)[((size_t)h * 1024 + (i0g + il) * 32) / 4 + j4];
            int e = il * 64 + h;
            Ws[j4 * 4 + 0][e] = v.x;
            Ws[j4 * 4 + 1][e] = v.y;
            Ws[j4 * 4 + 2][e] = v.z;
            Ws[j4 * 4 + 3][e] = v.w;
        }
    }
    __syncthreads();

    ulonglong2 acc[8][2];
    #pragma unroll
    for (int r = 0; r < 8; ++r) {
        acc[r][0].x = acc[r][0].y = 0ull;
        acc[r][1].x = acc[r][1].y = 0ull;
    }
    #pragma unroll 8
    for (int j = 0; j < 32; ++j) {
        ulonglong2 w0 = *(const ulonglong2*)&Ws[j][e0];
        ulonglong2 w1 = *(const ulonglong2*)&Ws[j][e0 + 4];
        #pragma unroll
        for (int r = 0; r < 8; ++r) {
            float f = Fs[(p0 + r) * FS_PAD + j];
            unsigned long long s;
            unsigned int fb = __float_as_uint(f);
            asm("mov.b64 %0, {%1, %1};" : "=l"(s) : "r"(fb));
            asm("fma.rn.f32x2 %0, %1, %2, %0;" : "+l"(acc[r][0].x) : "l"(s), "l"(w0.x));
            asm("fma.rn.f32x2 %0, %1, %2, %0;" : "+l"(acc[r][0].y) : "l"(s), "l"(w0.y));
            asm("fma.rn.f32x2 %0, %1, %2, %0;" : "+l"(acc[r][1].x) : "l"(s), "l"(w1.x));
            asm("fma.rn.f32x2 %0, %1, %2, %0;" : "+l"(acc[r][1].y) : "l"(s), "l"(w1.y));
        }
    }

    // epilogue: bf16 hi/mid split, packed pairs, k2 = h/2
    int il = e0 >> 6, i = i0g + il;
    int k2b = (e0 & 63) >> 1;
    #pragma unroll
    for (int r = 0; r < 8; ++r) {
        int p = pbase + p0 + r;
        uint4 vh, vm;
        split_u64(acc[r][0].x, vh.x, vm.x);
        split_u64(acc[r][0].y, vh.y, vm.y);
        split_u64(acc[r][1].x, vh.z, vm.z);
        split_u64(acc[r][1].y, vh.w, vm.w);
        size_t o = ((size_t)p * 32 + i) * 32 + k2b;
        *(uint4*)(g_Gh + o) = vh;
        *(uint4*)(g_Gm + o) = vm;
    }
}

// ===========================================================================
// Pair kernel: bf16 3-product MMA, 2 points per block, 512 blocks, 256 thr.
// Warp w computes rows 32w..32w+31 (two m16 tiles) for both points.
// Smem floats: Ut[64][260] | Gh0,Gm0,Gh1,Gm1[32][36](u32) | Ub0,Ub1 | Bf0,Bf1
// Stage (pitch 36) reuses Ut region after mainloop.
// ===========================================================================
#define UT_P 260
#define G_P  36
#define O_UT  0
#define O_G0H 16640
#define O_G0M (O_G0H + 1152)
#define O_G1H (O_G0M + 1152)
#define O_G1M (O_G1H + 1152)
#define O_UB0 (O_G1M + 1152)
#define O_UB1 (O_UB0 + 64)
#define O_BF0 (O_UB1 + 64)
#define O_BF1 (O_BF0 + 32)
#define SMF   (O_BF1 + 32)      // 21440 floats = 85760 B

__global__ void __launch_bounds__(256, 2) pair_kernel(float* __restrict__ out) {
    extern __shared__ float sm[];
    int blk = blockIdx.x;
    int p0 = blk * 2;
    int z = p0 >> 8, b0 = p0 & 255;
    int t = threadIdx.x, lane = t & 31, wid = t >> 5;
    int g = lane >> 2, tq = lane & 3;

    // ---- fills ----
    const float4* utsrc = (const float4*)(g_UT + (size_t)z * 64 * 256);
    #pragma unroll
    for (int it = 0; it < 16; ++it) {
        int idx = it * 256 + t;
        int h = idx >> 6, a4 = idx & 63;
        float4 v = utsrc[h * 64 + a4];
        *(float4*)(sm + O_UT + h * UT_P + a4 * 4) = v;
    }
    {
        int i = t >> 3, kq = (t & 7) * 4;
        size_t s0 = ((size_t)p0 * 32 + i) * 32 + kq;
        size_t s1 = ((size_t)(p0 + 1) * 32 + i) * 32 + kq;
        int d = i * G_P + kq;
        *(uint4*)(sm + O_G0H + d) = *(const uint4*)(g_Gh + s0);
        *(uint4*)(sm + O_G0M + d) = *(const uint4*)(g_Gm + s0);
        *(uint4*)(sm + O_G1H + d) = *(const uint4*)(g_Gh + s1);
        *(uint4*)(sm + O_G1M + d) = *(const uint4*)(g_Gm + s1);
    }
    if (t < 64) sm[O_UB0 + t] = g_Ub[p0 * 64 + t];
    else if (t < 128) sm[O_UB1 + t - 64] = g_Ub[(p0 + 1) * 64 + (t - 64)];
    else if (t < 160) sm[O_BF0 + t - 128] = g_Bf[p0 * 32 + (t - 128)];
    else if (t < 192) sm[O_BF1 + t - 160] = g_Bf[(p0 + 1) * 32 + (t - 160)];
    __syncthreads();

    float acc[2][2][4][4];
    #pragma unroll
    for (int pt = 0; pt < 2; ++pt)
        #pragma unroll
        for (int mi = 0; mi < 2; ++mi)
            #pragma unroll
            for (int n = 0; n < 4; ++n)
                acc[pt][mi][n][0] = acc[pt][mi][n][1] =
                acc[pt][mi][n][2] = acc[pt][mi][n][3] = 0.f;

    // ---- mainloop: 4 k16 steps ----
    #pragma unroll
    for (int s = 0; s < 4; ++s) {
        int kb = 16 * s;
        // U values for A frags: [mi][j][pair]
        float u[2][4][2];
        #pragma unroll
        for (int mi = 0; mi < 2; ++mi) {
            int rb = wid * 32 + mi * 16 + g;
            #pragma unroll
            for (int j = 0; j < 4; ++j) {
                int row = rb + (j & 1) * 8;
                int col = kb + 2 * tq + (j >> 1) * 8;
                u[mi][j][0] = sm[O_UT + col * UT_P + row];
                u[mi][j][1] = sm[O_UT + (col + 1) * UT_P + row];
            }
        }
        #pragma unroll
        for (int pt = 0; pt < 2; ++pt) {
            const float* ubp = sm + (pt ? O_UB1 : O_UB0) + kb + 2 * tq;
            float ubL0 = ubp[0], ubL1 = ubp[1];
            float ubH0 = ubp[8], ubH1 = ubp[9];
            uint32_t Ah[2][4], Am[2][4];
            #pragma unroll
            for (int mi = 0; mi < 2; ++mi) {
                #pragma unroll
                for (int j = 0; j < 4; ++j) {
                    float e0 = (j >> 1) ? ubH0 : ubL0;
                    float e1 = (j >> 1) ? ubH1 : ubL1;
                    float h0 = fmaxf(e0 - u[mi][j][0], 0.f);
                    float h1 = fmaxf(e1 - u[mi][j][1], 0.f);
                    uint32_t ph = bf16x2_of(h0, h1);
                    Ah[mi][j] = ph;
                    Am[mi][j] = bf16x2_of(h0 - bf_lo(ph), h1 - bf_hi(ph));
                }
            }
            const float* Gh = sm + (pt ? O_G1H : O_G0H);
            const float* Gm = sm + (pt ? O_G1M : O_G0M);
            #pragma unroll
            for (int n = 0; n < 4; ++n) {
                int bi = (n * 8 + g) * G_P + 8 * s + tq;
                uint32_t bh0 = __float_as_uint(Gh[bi]);
                uint32_t bh1 = __float_as_uint(Gh[bi + 4]);
                uint32_t bm0 = __float_as_uint(Gm[bi]);
                uint32_t bm1 = __float_as_uint(Gm[bi + 4]);
                #pragma unroll
                for (int mi = 0; mi < 2; ++mi) {
                    mma_bf16(acc[pt][mi][n], Ah[mi][0], Ah[mi][1], Ah[mi][2], Ah[mi][3], bh0, bh1);
                    mma_bf16(acc[pt][mi][n], Ah[mi][0], Ah[mi][1], Ah[mi][2], Ah[mi][3], bm0, bm1);
                    mma_bf16(acc[pt][mi][n], Am[mi][0], Am[mi][1], Am[mi][2], Am[mi][3], bh0, bh1);
                }
            }
        }
    }
    __syncthreads();   // Ut dead -> reuse as stage

    // ---- epilogue per point: stage -> +Bf -> coalesced STG.128 ----
    float* st = sm + O_UT;
    #pragma unroll
    for (int pt = 0; pt < 2; ++pt) {
        #pragma unroll
        for (int mi = 0; mi < 2; ++mi) {
            int row = wid * 32 + mi * 16 + g;
            #pragma unroll
            for (int n = 0; n < 4; ++n) {
                int col = n * 8 + 2 * tq;
                float2 v0 = {acc[pt][mi][n][0], acc[pt][mi][n][1]};
                float2 v1 = {acc[pt][mi][n][2], acc[pt][mi][n][3]};
                *(float2*)(st + row * G_P + col) = v0;
                *(float2*)(st + (row + 8) * G_P + col) = v1;
            }
        }
        __syncthreads();
        const float* bfp = sm + (pt ? O_BF1 : O_BF0);
        int b = b0 + pt;
        #pragma unroll
        for (int it = 0; it < 8; ++it) {
            int idx = it * 256 + t;
            int row = idx >> 3, c4 = idx & 7;
            float4 v = *(const float4*)(st + row * G_P + c4 * 4);
            float4 bf = *(const float4*)(bfp + c4 * 4);
            v.x += bf.x; v.y += bf.y; v.z += bf.z; v.w += bf.w;
            *(float4*)(out + (((size_t)(z * 256 + row)) * 256 + b) * 32 + c4 * 4) = v;
        }
        __syncthreads();
    }
}

// ===========================================================================
extern "C" void kernel_launch(void* const* d_in, const int* in_sizes, int n_in,
                              void* d_out, int out_size) {
    const float* feat = (const float*)d_in[0];
    const float* geo  = (const float*)d_in[1];
    const float* W1   = (const float*)d_in[2];
    const float* b1   = (const float*)d_in[3];
    const float* W2   = (const float*)d_in[4];
    const float* b2   = (const float*)d_in[5];
    float* out = (float*)d_out;

    cudaFuncSetAttribute(pair_kernel, cudaFuncAttributeMaxDynamicSharedMemorySize,
                         SMF * 4);

    pre_all<<<dim3(16, 8), 256>>>(geo, feat, W1, b1, W2, b2);
    pair_kernel<<<512, 256, SMF * 4>>>(out);
}